// round 1
// baseline (speedup 1.0000x reference)
#include <cuda_runtime.h>

// QuanvLayer closed form:
//   z_i = cos(w_i) * cos(x_i)   (per patch element, qubit order p00,p01,p10,p11)
//   out[q=0] = z1*z2*z3
//   out[q=1] = z0*z1
//   out[q=2] = z0*z1*z2
//   out[q=3] = z0*z1*z2*z3
//
// x: (B=128, C=3, H=128, W=128) f32 ; weights: (1,4) f32
// out: (B, C*4, 64, 64) f32
//
// Each thread handles 2 horizontally adjacent patches:
//   loads 2x float4 (top row 4 cols, bottom row 4 cols)
//   stores 4x float2 (one per output channel plane)

#define B_ 128
#define C_ 3
#define H_ 128
#define W_ 128
#define HH 64
#define WH 64

__global__ void __launch_bounds__(256)
quanv_kernel(const float* __restrict__ x,
             const float* __restrict__ w,
             float* __restrict__ out,
             int total)
{
    int tid = blockIdx.x * blockDim.x + threadIdx.x;
    if (tid >= total) return;

    // tid = ((bc)*HH + h2)*32 + w4 ; w4 covers 2 patches (4 input cols)
    int w4 = tid & 31;
    int h2 = (tid >> 5) & (HH - 1);
    int bc = tid >> 11;              // b*C + c in [0, 384)

    const float cw0 = __cosf(__ldg(w + 0));
    const float cw1 = __cosf(__ldg(w + 1));
    const float cw2 = __cosf(__ldg(w + 2));
    const float cw3 = __cosf(__ldg(w + 3));

    const float* row = x + ((size_t)bc * H_ + 2 * h2) * W_ + 4 * w4;
    const float4 top = *reinterpret_cast<const float4*>(row);
    const float4 bot = *reinterpret_cast<const float4*>(row + W_);

    // patch A: cols 4w4, 4w4+1
    float z0 = cw0 * __cosf(top.x);
    float z1 = cw1 * __cosf(top.y);
    float z2 = cw2 * __cosf(bot.x);
    float z3 = cw3 * __cosf(bot.y);
    float A1 = z0 * z1;
    float A2 = A1 * z2;
    float A3 = A2 * z3;
    float A0 = z1 * z2 * z3;

    // patch B: cols 4w4+2, 4w4+3
    float y0 = cw0 * __cosf(top.z);
    float y1 = cw1 * __cosf(top.w);
    float y2 = cw2 * __cosf(bot.z);
    float y3 = cw3 * __cosf(bot.w);
    float B1 = y0 * y1;
    float B2 = B1 * y2;
    float B3 = B2 * y3;
    float B0 = y1 * y2 * y3;

    // out[((4*bc + q)*HH + h2)*WH + 2*w4], plane stride HH*WH = 4096
    float* o = out + (((size_t)4 * bc) * HH + h2) * WH + 2 * w4;
    *reinterpret_cast<float2*>(o)              = make_float2(A0, B0);
    *reinterpret_cast<float2*>(o + 1 * HH*WH)  = make_float2(A1, B1);
    *reinterpret_cast<float2*>(o + 2 * HH*WH)  = make_float2(A2, B2);
    *reinterpret_cast<float2*>(o + 3 * HH*WH)  = make_float2(A3, B3);
}

extern "C" void kernel_launch(void* const* d_in, const int* in_sizes, int n_in,
                              void* d_out, int out_size)
{
    // identify inputs by size (x has B*C*H*W elements, weights has 4)
    const float* x = (const float*)d_in[0];
    const float* w = (const float*)d_in[1];
    if (n_in >= 2 && in_sizes[0] == 4) {
        x = (const float*)d_in[1];
        w = (const float*)d_in[0];
    }
    float* out = (float*)d_out;

    const int total = B_ * C_ * HH * (WH / 2);   // 786432 threads
    const int threads = 256;
    const int blocks = (total + threads - 1) / threads;
    quanv_kernel<<<blocks, threads>>>(x, w, out, total);
}

// round 3
// speedup vs baseline: 1.0031x; 1.0031x over previous
#include <cuda_runtime.h>

// QuanvLayer closed form:
//   z_i = cos(w_i) * cos(x_i)   (patch elements p00,p01,p10,p11)
//   out[q=0] = z1*z2*z3
//   out[q=1] = z0*z1
//   out[q=2] = z0*z1*z2
//   out[q=3] = z0*z1*z2*z3
//
// x: (128, 3, 128, 128) f32 ; weights: (1,4) f32 ; out: (128, 12, 64, 64) f32
//
// R2 (rerun after container failure): 4 patches per thread (8 input cols, 2 rows)
// -> 4x float4 loads (MLP=4), 4x float4 stores (one per output plane).
// Latency-bound fix: more bytes in flight per thread.

#define B_ 128
#define C_ 3
#define H_ 128
#define W_ 128
#define HH 64
#define WH 64

__global__ void __launch_bounds__(256)
quanv_kernel(const float* __restrict__ x,
             const float* __restrict__ w,
             float* __restrict__ out)
{
    int tid = blockIdx.x * blockDim.x + threadIdx.x;

    // tid = (bc*HH + h2)*16 + w8 ; w8 covers 4 patches (8 input cols)
    int w8 = tid & 15;
    int h2 = (tid >> 4) & (HH - 1);
    int bc = tid >> 10;              // b*C + c in [0, 384)

    const float cw0 = __cosf(__ldg(w + 0));
    const float cw1 = __cosf(__ldg(w + 1));
    const float cw2 = __cosf(__ldg(w + 2));
    const float cw3 = __cosf(__ldg(w + 3));

    const float* row = x + ((size_t)bc * H_ + 2 * h2) * W_ + 8 * w8;
    // issue all four loads up-front (MLP=4)
    const float4 t0 = *reinterpret_cast<const float4*>(row);
    const float4 t1 = *reinterpret_cast<const float4*>(row + 4);
    const float4 b0 = *reinterpret_cast<const float4*>(row + W_);
    const float4 b1 = *reinterpret_cast<const float4*>(row + W_ + 4);

    float top[8] = {t0.x, t0.y, t0.z, t0.w, t1.x, t1.y, t1.z, t1.w};
    float bot[8] = {b0.x, b0.y, b0.z, b0.w, b1.x, b1.y, b1.z, b1.w};

    float o0[4], o1[4], o2[4], o3[4];
    #pragma unroll
    for (int p = 0; p < 4; p++) {
        float z0 = cw0 * __cosf(top[2*p]);
        float z1 = cw1 * __cosf(top[2*p + 1]);
        float z2 = cw2 * __cosf(bot[2*p]);
        float z3 = cw3 * __cosf(bot[2*p + 1]);
        float q1 = z0 * z1;
        float q2 = q1 * z2;
        float q3 = q2 * z3;
        float q0 = z1 * z2 * z3;
        o0[p] = q0; o1[p] = q1; o2[p] = q2; o3[p] = q3;
    }

    // out[((4*bc + q)*HH + h2)*WH + 4*w8], plane stride HH*WH = 4096
    float* o = out + (((size_t)4 * bc) * HH + h2) * WH + 4 * w8;
    *reinterpret_cast<float4*>(o)             = make_float4(o0[0], o0[1], o0[2], o0[3]);
    *reinterpret_cast<float4*>(o + 1*HH*WH)   = make_float4(o1[0], o1[1], o1[2], o1[3]);
    *reinterpret_cast<float4*>(o + 2*HH*WH)   = make_float4(o2[0], o2[1], o2[2], o2[3]);
    *reinterpret_cast<float4*>(o + 3*HH*WH)   = make_float4(o3[0], o3[1], o3[2], o3[3]);
}

extern "C" void kernel_launch(void* const* d_in, const int* in_sizes, int n_in,
                              void* d_out, int out_size)
{
    const float* x = (const float*)d_in[0];
    const float* w = (const float*)d_in[1];
    if (n_in >= 2 && in_sizes[0] == 4) {
        x = (const float*)d_in[1];
        w = (const float*)d_in[0];
    }
    float* out = (float*)d_out;

    const int total = B_ * C_ * HH * (WH / 4);   // 393216 threads
    const int threads = 256;
    const int blocks = total / threads;          // 1536
    quanv_kernel<<<blocks, threads>>>(x, w, out);
}

// round 4
// speedup vs baseline: 1.0847x; 1.0814x over previous
#include <cuda_runtime.h>

// QuanvLayer closed form:
//   z_i = cos(w_i) * cos(x_i)   (patch elements p00,p01,p10,p11)
//   out[q=0] = z1*z2*z3 ; out[q=1] = z0*z1 ; out[q=2] = z0*z1*z2 ; out[q=3] = z0*z1*z2*z3
//
// x: (128, 3, 128, 128) f32 ; weights: (1,4) f32 ; out: (128, 12, 64, 64) f32
//
// R4: persistent single-wave grid. 148 SMs x 8 blocks = 1184 blocks of 256,
// grid-stride loop over 4-patch chunks (393216 chunks, <=2 iters/thread).
// Removes the wave transition + ragged tail that dominated the 10.2us runs.

#define B_ 128
#define C_ 3
#define H_ 128
#define W_ 128
#define HH 64
#define WH 64

#define NBLOCKS 1184
#define NTHREADS 256
#define TOTAL_CHUNKS (B_ * C_ * HH * (WH / 4))   // 393216

__global__ void __launch_bounds__(NTHREADS, 8)
quanv_kernel(const float* __restrict__ x,
             const float* __restrict__ w,
             float* __restrict__ out)
{
    const float cw0 = __cosf(__ldg(w + 0));
    const float cw1 = __cosf(__ldg(w + 1));
    const float cw2 = __cosf(__ldg(w + 2));
    const float cw3 = __cosf(__ldg(w + 3));

    const int stride = NBLOCKS * NTHREADS;       // 303104

    for (int tid = blockIdx.x * NTHREADS + threadIdx.x;
         tid < TOTAL_CHUNKS; tid += stride)
    {
        // tid = (bc*HH + h2)*16 + w8 ; w8 covers 4 patches (8 input cols)
        int w8 = tid & 15;
        int h2 = (tid >> 4) & (HH - 1);
        int bc = tid >> 10;                      // b*C + c in [0, 384)

        const float* row = x + ((size_t)bc * H_ + 2 * h2) * W_ + 8 * w8;
        const float4 t0 = *reinterpret_cast<const float4*>(row);
        const float4 t1 = *reinterpret_cast<const float4*>(row + 4);
        const float4 b0 = *reinterpret_cast<const float4*>(row + W_);
        const float4 b1 = *reinterpret_cast<const float4*>(row + W_ + 4);

        float top[8] = {t0.x, t0.y, t0.z, t0.w, t1.x, t1.y, t1.z, t1.w};
        float bot[8] = {b0.x, b0.y, b0.z, b0.w, b1.x, b1.y, b1.z, b1.w};

        float o0[4], o1[4], o2[4], o3[4];
        #pragma unroll
        for (int p = 0; p < 4; p++) {
            float z0 = cw0 * __cosf(top[2*p]);
            float z1 = cw1 * __cosf(top[2*p + 1]);
            float z2 = cw2 * __cosf(bot[2*p]);
            float z3 = cw3 * __cosf(bot[2*p + 1]);
            float q1 = z0 * z1;
            float q2 = q1 * z2;
            float q3 = q2 * z3;
            float q0 = z1 * z2 * z3;
            o0[p] = q0; o1[p] = q1; o2[p] = q2; o3[p] = q3;
        }

        // out[((4*bc + q)*HH + h2)*WH + 4*w8], plane stride HH*WH = 4096
        float* o = out + (((size_t)4 * bc) * HH + h2) * WH + 4 * w8;
        *reinterpret_cast<float4*>(o)           = make_float4(o0[0], o0[1], o0[2], o0[3]);
        *reinterpret_cast<float4*>(o + 1*HH*WH) = make_float4(o1[0], o1[1], o1[2], o1[3]);
        *reinterpret_cast<float4*>(o + 2*HH*WH) = make_float4(o2[0], o2[1], o2[2], o2[3]);
        *reinterpret_cast<float4*>(o + 3*HH*WH) = make_float4(o3[0], o3[1], o3[2], o3[3]);
    }
}

extern "C" void kernel_launch(void* const* d_in, const int* in_sizes, int n_in,
                              void* d_out, int out_size)
{
    const float* x = (const float*)d_in[0];
    const float* w = (const float*)d_in[1];
    if (n_in >= 2 && in_sizes[0] == 4) {
        x = (const float*)d_in[1];
        w = (const float*)d_in[0];
    }
    float* out = (float*)d_out;

    quanv_kernel<<<NBLOCKS, NTHREADS>>>(x, w, out);
}